// round 17
// baseline (speedup 1.0000x reference)
#include <cuda_runtime.h>
#include <cuda_fp16.h>
#include <cstdint>

// MeshConv via mma.sync m16n8k16 fp16 single-term (rel_err ~3e-4).
// Direct-LDG full-line gather straight into compute lanes' registers.
// 5 CTAs/SM (reg-capped at 102) for latency coverage.

#define NK      160
#define TILE_E  128
#define THREADS 128
#define RSTRIDE 336                      // A row stride bytes
#define A_BYTES (TILE_E * RSTRIDE)       // 43008
#define SM_A    0
#define SM_IDX  A_BYTES                  // 43008
#define SM_TOTAL (SM_IDX + TILE_E * 4 * 4)   // 45056
#define WF_N    (10 * 8 * 32)

__device__ uint2 g_Wfrag[WF_N];          // {b0, b1} fp16x2
__device__ int   g_nbr64;

__device__ __forceinline__ uint32_t pk_f16x2(float lo, float hi) {
    uint32_t r;
    asm("cvt.rn.f16x2.f32 %0, %1, %2;" : "=r"(r) : "f"(hi), "f"(lo));
    return r;
}

__global__ void meshconv_prep(const float* __restrict__ W,
                              const void* __restrict__ nbr_raw, int E) {
    int i = blockIdx.x * blockDim.x + threadIdx.x;
    if (i < WF_N) {
        int lane = i & 31;
        int n    = (i >> 5) & 7;
        int ks   = i >> 8;
        int ng = n * 8 + (lane >> 2);
        int k0 = ks * 16 + (lane & 3) * 2;
        uint2 f;
        f.x = pk_f16x2(W[ng * NK + k0],     W[ng * NK + k0 + 1]);
        f.y = pk_f16x2(W[ng * NK + k0 + 8], W[ng * NK + k0 + 9]);
        g_Wfrag[i] = f;
    }
    if (i == 0) {
        const long long* p = (const long long*)nbr_raw;
        int ok = 1;
        #pragma unroll
        for (int j = 0; j < 16; j++) {
            long long v = p[j];
            if (v < -(long long)E || v >= (long long)E) ok = 0;
        }
        g_nbr64 = ok;
    }
}

__device__ __forceinline__ uint32_t smem_u32(const void* p) {
    uint32_t a;
    asm("{ .reg .u64 t; cvta.to.shared.u64 t, %1; cvt.u32.u64 %0, t; }" : "=r"(a) : "l"(p));
    return a;
}
__device__ __forceinline__ void ldsm_x4(uint32_t* r, uint32_t addr) {
    asm volatile("ldmatrix.sync.aligned.m8n8.x4.shared.b16 {%0,%1,%2,%3}, [%4];"
                 : "=r"(r[0]), "=r"(r[1]), "=r"(r[2]), "=r"(r[3]) : "r"(addr));
}
__device__ __forceinline__ void mma_f16(float* d, const uint32_t* a,
                                        uint32_t b0, uint32_t b1) {
    asm volatile(
        "mma.sync.aligned.m16n8k16.row.col.f32.f16.f16.f32 "
        "{%0,%1,%2,%3}, {%4,%5,%6,%7}, {%8,%9}, {%0,%1,%2,%3};"
        : "+f"(d[0]), "+f"(d[1]), "+f"(d[2]), "+f"(d[3])
        : "r"(a[0]), "r"(a[1]), "r"(a[2]), "r"(a[3]), "r"(b0), "r"(b1));
}

__global__ __launch_bounds__(THREADS, 5)
void meshconv_kernel(const float* __restrict__ x,
                     const void* __restrict__ nbr_raw,
                     const float* __restrict__ bias,
                     float* __restrict__ out, int E) {
    extern __shared__ char smem[];
    const uint32_t sbase = smem_u32(smem);
    const int tid  = threadIdx.x;
    const int lane = tid & 31;
    const int warp = tid >> 5;
    int* sIdx = (int*)(smem + SM_IDX);

    const int e0 = blockIdx.x * TILE_E;

    // ---- resolve neighbor indices once ----
    {
        const int er = (e0 + tid) < E ? (e0 + tid) : (E - 1);
        long long n[4];
        if (g_nbr64) {
            const long long* nb = (const long long*)nbr_raw + (size_t)er * 4;
            n[0] = nb[0]; n[1] = nb[1]; n[2] = nb[2]; n[3] = nb[3];
        } else {
            const int* nb = (const int*)nbr_raw + (size_t)er * 4;
            n[0] = nb[0]; n[1] = nb[1]; n[2] = nb[2]; n[3] = nb[3];
        }
        int4 w;
        w.x = (n[0] < 0) ? -1 : (n[0] >= E ? E - 1 : (int)n[0]);
        w.y = (n[1] < 0) ? -1 : (n[1] >= E ? E - 1 : (int)n[1]);
        w.z = (n[2] < 0) ? -1 : (n[2] >= E ? E - 1 : (int)n[2]);
        w.w = (n[3] < 0) ? -1 : (n[3] >= E ? E - 1 : (int)n[3]);
        *(int4*)(sIdx + tid * 4) = w;
    }
    __syncwarp();

    // compute roles: el = lane>>3 (element within chunk), sl = lane&7 (16B slice)
    const int el = lane >> 3, sl = lane & 7;
    char* aW = smem + SM_A;

    #pragma unroll
    for (int ch = 0; ch < 8; ch++) {
        const int egl = warp * 32 + ch * 4 + el;
        const int erg = (e0 + egl) < E ? (e0 + egl) : (E - 1);

        int4 nb = *(const int4*)(sIdx + egl * 4);
        float m0 = nb.x >= 0 ? 1.0f : 0.0f;  int r0 = nb.x >= 0 ? nb.x : 0;
        float m1 = nb.y >= 0 ? 1.0f : 0.0f;  int r1 = nb.y >= 0 ? nb.y : 0;
        float m2 = nb.z >= 0 ? 1.0f : 0.0f;  int r2 = nb.z >= 0 ? nb.z : 0;
        float m3 = nb.w >= 0 ? 1.0f : 0.0f;  int r3 = nb.w >= 0 ? nb.w : 0;

        float4 A0 = __ldg((const float4*)(x + (size_t)r0 * 32 + sl * 4));
        float4 A1 = __ldg((const float4*)(x + (size_t)r1 * 32 + sl * 4));
        float4 B0 = __ldg((const float4*)(x + (size_t)r2 * 32 + sl * 4));
        float4 B1 = __ldg((const float4*)(x + (size_t)r3 * 32 + sl * 4));
        float4 XV = __ldg((const float4*)(x + (size_t)erg * 32 + sl * 4));

        float a0[4] = {A0.x * m0, A0.y * m0, A0.z * m0, A0.w * m0};
        float a1[4] = {A1.x * m1, A1.y * m1, A1.z * m1, A1.w * m1};
        float b0[4] = {B0.x * m2, B0.y * m2, B0.z * m2, B0.w * m2};
        float b1[4] = {B1.x * m3, B1.y * m3, B1.z * m3, B1.w * m3};

        float g1[4], g2[4], g3[4], g4[4];
        #pragma unroll
        for (int j = 0; j < 4; j++) {
            float sa = a0[j] + a1[j], sb = b0[j] + b1[j];
            float da = fabsf(a0[j] - a1[j]), db = fabsf(b0[j] - b1[j]);
            g1[j] = sa + sb;
            g2[j] = da + db;
            g3[j] = fabsf(sa - sb);
            g4[j] = fabsf(da - db);
        }

        char* arow = aW + egl * RSTRIDE + sl * 8;
        *(uint2*)(arow + 0 * 64) = make_uint2(pk_f16x2(XV.x, XV.y), pk_f16x2(XV.z, XV.w));
        *(uint2*)(arow + 1 * 64) = make_uint2(pk_f16x2(g1[0], g1[1]), pk_f16x2(g1[2], g1[3]));
        *(uint2*)(arow + 2 * 64) = make_uint2(pk_f16x2(g2[0], g2[1]), pk_f16x2(g2[2], g2[3]));
        *(uint2*)(arow + 3 * 64) = make_uint2(pk_f16x2(g3[0], g3[1]), pk_f16x2(g3[2], g3[3]));
        *(uint2*)(arow + 4 * 64) = make_uint2(pk_f16x2(g4[0], g4[1]), pk_f16x2(g4[2], g4[3]));
    }
    __syncwarp();   // STS visible to ldsm

    // ---- MMA over own 32 rows: single term ----
    float acc[2][8][4];
    #pragma unroll
    for (int st = 0; st < 2; st++)
        #pragma unroll
        for (int nn = 0; nn < 8; nn++)
            #pragma unroll
            for (int q = 0; q < 4; q++) acc[st][nn][q] = 0.0f;

    const uint32_t arow = (uint32_t)(warp * 32 + (lane & 15));
    const uint32_t aoff = ((uint32_t)(lane >> 4)) * 16;
    const uint32_t a0p = sbase + SM_A + arow * RSTRIDE + aoff;
    const uint32_t a1p = a0p + 16 * RSTRIDE;

    #pragma unroll
    for (int ks = 0; ks < 10; ks++) {
        uint32_t f0[4], f1[4];
        ldsm_x4(f0, a0p + ks * 32);
        ldsm_x4(f1, a1p + ks * 32);
        #pragma unroll
        for (int nn = 0; nn < 8; nn++) {
            uint2 f = __ldg(&g_Wfrag[(ks * 8 + nn) * 32 + lane]);
            mma_f16(acc[0][nn], f0, f.x, f.y);
            mma_f16(acc[1][nn], f1, f.x, f.y);
        }
    }

    // ---- Epilogue ----
    const int colq = (lane & 3) * 2;
    #pragma unroll
    for (int nn = 0; nn < 8; nn++) {
        int col = nn * 8 + colq;
        float2 bv = *(const float2*)(bias + col);
        #pragma unroll
        for (int st = 0; st < 2; st++) {
            int rbase = e0 + warp * 32 + st * 16 + (lane >> 2);
            if (rbase < E) {
                float2 o0 = make_float2(acc[st][nn][0] + bv.x, acc[st][nn][1] + bv.y);
                *(float2*)(out + (size_t)rbase * 64 + col) = o0;
            }
            if (rbase + 8 < E) {
                float2 o1 = make_float2(acc[st][nn][2] + bv.x, acc[st][nn][3] + bv.y);
                *(float2*)(out + (size_t)(rbase + 8) * 64 + col) = o1;
            }
        }
    }
}

extern "C" void kernel_launch(void* const* d_in, const int* in_sizes, int n_in,
                              void* d_out, int out_size) {
    const int E = out_size / 64;
    const float* x = nullptr; const void* nbr = nullptr;
    const float* W = nullptr; const float* b = nullptr;

    for (int i = 0; i < n_in; i++) {
        long long sz = in_sizes[i];
        if (sz == (long long)E * 32)      x   = (const float*)d_in[i];
        else if (sz == (long long)E * 4)  nbr = d_in[i];
        else if (sz == 64 * NK)           W   = (const float*)d_in[i];
        else if (sz == 64)                b   = (const float*)d_in[i];
    }
    float* out = (float*)d_out;

    meshconv_prep<<<(WF_N + 255) / 256, 256>>>(W, nbr, E);

    cudaFuncSetAttribute(meshconv_kernel,
                         cudaFuncAttributeMaxDynamicSharedMemorySize, SM_TOTAL);
    int nb = (E + TILE_E - 1) / TILE_E;
    meshconv_kernel<<<nb, THREADS, SM_TOTAL>>>(x, nbr, b, out, E);
}